// round 1
// baseline (speedup 1.0000x reference)
#include <cuda_runtime.h>
#include <cuda_bf16.h>

// SegmentalEmotion: per-sample sliding-window segment means.
// H: [B, T, D] fp32, lengths_sec: [B] fp32.
// Output: S_pad [B, maxS, D] fp32 (+ optional mask [B, maxS] fp32 appended,
// auto-detected from out_size).
//
// Plan replicated on-device in fp64 (bitwise-matches numpy):
//   dur = max(len, 0.001); fps = T/dur
//   win = max(1, rint(fps*1.0)); hop = max(1, rint(fps*0.5))
//   n = (T >= win) ? (T-win)/hop + 1 : 0 ; fallback -> single full-T mean
//   segment s: [s*hop, s*hop+win) clamped to T; mean over count frames.

#define T_FRAMES 1500
#define D_DIM    768
#define NTHREADS 192   // D_DIM / 4 float4 lanes

__global__ __launch_bounds__(NTHREADS)
void seg_mean_kernel(const float* __restrict__ H,
                     const float* __restrict__ lens,
                     float* __restrict__ S,      // [B, maxS, D]
                     float* __restrict__ Mout,   // [B, maxS] or nullptr
                     int maxS)
{
    const int s = blockIdx.x;
    const int b = blockIdx.y;
    const int tid = threadIdx.x;

    // ---- per-sample window plan (fp64, matches numpy exactly) ----
    double dur = fmax((double)lens[b], 0.001);
    double fps = (double)T_FRAMES / dur;
    long long win = (long long)rint(fps);        // WIN_SEC = 1.0
    if (win < 1) win = 1;
    long long hop = (long long)rint(fps * 0.5);  // HOP_SEC = 0.5
    if (hop < 1) hop = 1;

    long long n = ((long long)T_FRAMES >= win)
                      ? ((long long)T_FRAMES - win) / hop + 1
                      : 0;
    const bool fallback = (n == 0);
    const long long n_eff = fallback ? 1 : n;
    const bool valid = ((long long)s < n_eff);

    float4* outRow = (float4*)(S + ((size_t)b * maxS + s) * D_DIM);

    if (!valid) {
        outRow[tid] = make_float4(0.f, 0.f, 0.f, 0.f);
        if (Mout != nullptr && tid == 0)
            Mout[(size_t)b * maxS + s] = 0.f;
        return;
    }

    long long start, end;
    if (fallback) {
        start = 0;
        end = T_FRAMES;
    } else {
        start = (long long)s * hop;
        end = start + win;
        if (start > T_FRAMES) start = T_FRAMES;
        if (end > T_FRAMES) end = T_FRAMES;
    }
    long long cnt = end - start;
    if (cnt < 1) cnt = 1;
    const float inv = 1.0f / (float)cnt;

    const float4* __restrict__ Hb =
        (const float4*)H + (size_t)b * T_FRAMES * (D_DIM / 4) + tid;

    float4 acc = make_float4(0.f, 0.f, 0.f, 0.f);
    long long t = start;
    // unrolled-by-4 main loop for memory-level parallelism
    for (; t + 4 <= end; t += 4) {
        float4 v0 = Hb[(t + 0) * (D_DIM / 4)];
        float4 v1 = Hb[(t + 1) * (D_DIM / 4)];
        float4 v2 = Hb[(t + 2) * (D_DIM / 4)];
        float4 v3 = Hb[(t + 3) * (D_DIM / 4)];
        acc.x += v0.x; acc.y += v0.y; acc.z += v0.z; acc.w += v0.w;
        acc.x += v1.x; acc.y += v1.y; acc.z += v1.z; acc.w += v1.w;
        acc.x += v2.x; acc.y += v2.y; acc.z += v2.z; acc.w += v2.w;
        acc.x += v3.x; acc.y += v3.y; acc.z += v3.z; acc.w += v3.w;
    }
    for (; t < end; ++t) {
        float4 v = Hb[t * (D_DIM / 4)];
        acc.x += v.x; acc.y += v.y; acc.z += v.z; acc.w += v.w;
    }

    outRow[tid] = make_float4(acc.x * inv, acc.y * inv, acc.z * inv, acc.w * inv);
    if (Mout != nullptr && tid == 0)
        Mout[(size_t)b * maxS + s] = 1.f;
}

extern "C" void kernel_launch(void* const* d_in, const int* in_sizes, int n_in,
                              void* d_out, int out_size)
{
    const float* H    = (const float*)d_in[0];
    const float* lens = (const float*)d_in[1];
    float* out        = (float*)d_out;

    const int B = in_sizes[1];  // 32

    // Infer maxS (and whether the mask is appended) from out_size.
    // out_size = B*maxS*(D+1) with mask, or B*maxS*D without.
    // 768 and 769 are coprime and maxS << 768, so exactly one divides.
    int maxS;
    bool has_mask;
    if (out_size % (B * (D_DIM + 1)) == 0) {
        maxS = out_size / (B * (D_DIM + 1));
        has_mask = true;
    } else {
        maxS = out_size / (B * D_DIM);
        has_mask = false;
    }

    float* Mout = has_mask ? (out + (size_t)B * maxS * D_DIM) : nullptr;

    dim3 grid(maxS, B);
    seg_mean_kernel<<<grid, NTHREADS>>>(H, lens, out, Mout, maxS);
}